// round 1
// baseline (speedup 1.0000x reference)
#include <cuda_runtime.h>
#include <math.h>

#define NB 32
#define NS 48000
#define L_CHUNK 320
#define WARMUP 1024
#define NCHUNK (NS / L_CHUNK)   /* 150 */

// Packed per-sample data: 15 biquad coefs + sustain input, layout [n][b][16]
__device__ float  g_data[(size_t)NS * NB * 16];
// Per-sample output mix: (alpha_a * y_attack, 1 - alpha_a), layout [n][b]
__device__ float2 g_mix[(size_t)NS * NB];

// ---------------------------------------------------------------------------
// Kernel 1: transient separation, waveshaper, RBJ coefficient precompute.
// Thread i -> (b = i / NS, n = i % NS); consecutive threads walk n (coalesced
// reads of all [B][N] inputs). Writes 64B contiguous per thread to g_data.
// ---------------------------------------------------------------------------
__global__ void prep_kernel(const float* __restrict__ x,
                            const float* __restrict__ alpha,
                            const float* __restrict__ beta,
                            const float* __restrict__ low_db,
                            const float* __restrict__ mid_db,
                            const float* __restrict__ mid_fc,
                            const float* __restrict__ mid_Q,
                            const float* __restrict__ high_db,
                            const float* __restrict__ alpha_a)
{
    int i = blockIdx.x * blockDim.x + threadIdx.x;
    if (i >= NB * NS) return;
    int b = i / NS;
    int n = i - b * NS;

    // ---- transient separation (15-tap moving average of |x|, zero padded) ----
    const float* xr = x + (size_t)b * NS;
    float xv = xr[n];
    float env = 0.0f;
    #pragma unroll
    for (int d = -7; d <= 7; ++d) {
        int j = n + d;
        if (j >= 0 && j < NS) env += fabsf(xr[j]);
    }
    env *= (1.0f / 15.0f);
    float xa   = fabsf(xv);
    float gate = 1.0f / (1.0f + expf(-8.0f * (xa - env)));
    float av   = gate * xv;            // attack
    float sv   = (1.0f - gate) * xv;   // sustain

    // ---- waveshaper on attack path ----
    float al_ = alpha[i];
    float be_ = beta[i];
    float ya  = tanhf(fmaf(al_, av, be_)) - tanhf(be_);

    // ---- RBJ coefficients ----
    const float LOG2_10_OVER_40 = 0.0830482024f;   // log2(10)/40
    float c[16];

    // low shelf, fc = 250 Hz (fixed)
    {
        const float cw = 0.9994645875f;   // cos(2*pi*250/48000)
        const float alc = 0.0231360485f;  // sin(w0)*sqrt(2)/2
        float A  = exp2f(low_db[i] * LOG2_10_OVER_40);
        float sA = sqrtf(A);
        float t  = 2.0f * sA * alc;
        float Ap1 = A + 1.0f, Am1 = A - 1.0f;
        float b0 = A * (Ap1 - Am1 * cw + t);
        float b1 = 2.0f * A * (Am1 - Ap1 * cw);
        float b2 = A * (Ap1 - Am1 * cw - t);
        float a0 = Ap1 + Am1 * cw + t;
        float a1 = -2.0f * (Am1 + Ap1 * cw);
        float a2 = Ap1 + Am1 * cw - t;
        float inv = 1.0f / a0;
        c[0] = b0 * inv; c[1] = b1 * inv; c[2] = b2 * inv;
        c[3] = a1 * inv; c[4] = a2 * inv;
    }

    // mid peaking EQ (fc, Q per sample)
    {
        float A  = exp2f(mid_db[i] * LOG2_10_OVER_40);
        float w0 = mid_fc[i] * 1.30899693e-4f;   // 2*pi/48000
        float sw, cw;
        sincosf(w0, &sw, &cw);
        float alq = sw / (2.0f * mid_Q[i]);
        float b0 = 1.0f + alq * A;
        float b1 = -2.0f * cw;
        float b2 = 1.0f - alq * A;
        float a0 = 1.0f + alq / A;
        float a2 = 1.0f - alq / A;
        float inv = 1.0f / a0;
        c[5] = b0 * inv; c[6] = b1 * inv; c[7] = b2 * inv;
        c[8] = b1 * inv; c[9] = a2 * inv;   // a1 == b1 for peaking EQ
    }

    // high shelf, fc = 4000 Hz (fixed)
    {
        const float cw = 0.8660254038f;   // cos(pi/6)
        const float alc = 0.3535533906f;  // sin(pi/6)*sqrt(2)/2
        float A  = exp2f(high_db[i] * LOG2_10_OVER_40);
        float sA = sqrtf(A);
        float t  = 2.0f * sA * alc;
        float Ap1 = A + 1.0f, Am1 = A - 1.0f;
        float b0 = A * (Ap1 + Am1 * cw + t);
        float b1 = -2.0f * A * (Am1 + Ap1 * cw);
        float b2 = A * (Ap1 + Am1 * cw - t);
        float a0 = Ap1 - Am1 * cw + t;
        float a1 = 2.0f * (Am1 - Ap1 * cw);
        float a2 = Ap1 - Am1 * cw - t;
        float inv = 1.0f / a0;
        c[10] = b0 * inv; c[11] = b1 * inv; c[12] = b2 * inv;
        c[13] = a1 * inv; c[14] = a2 * inv;
    }

    c[15] = sv;

    float4* dst = (float4*)(g_data + ((size_t)n * NB + b) * 16);
    dst[0] = make_float4(c[0],  c[1],  c[2],  c[3]);
    dst[1] = make_float4(c[4],  c[5],  c[6],  c[7]);
    dst[2] = make_float4(c[8],  c[9],  c[10], c[11]);
    dst[3] = make_float4(c[12], c[13], c[14], c[15]);

    float aav = alpha_a[i];
    g_mix[(size_t)n * NB + b] = make_float2(aav * ya, 1.0f - aav);
}

// ---------------------------------------------------------------------------
// One biquad-cascade step. q0..q3 = packed coefs, v in/out, 6 states by ref.
// ---------------------------------------------------------------------------
__device__ __forceinline__ float cascade_step(float4 q0, float4 q1, float4 q2, float4 q3,
                                              float& s11, float& s12,
                                              float& s21, float& s22,
                                              float& s31, float& s32)
{
    float v = q3.w;
    // low shelf: b0=q0.x b1=q0.y b2=q0.z a1=q0.w a2=q1.x
    float y = fmaf(q0.x, v, s11);
    s11 = fmaf(q0.y, v, fmaf(-q0.w, y, s12));
    s12 = fmaf(q0.z, v, -q1.x * y);
    v = y;
    // mid peak: b0=q1.y b1=q1.z b2=q1.w a1=q2.x a2=q2.y
    y = fmaf(q1.y, v, s21);
    s21 = fmaf(q1.z, v, fmaf(-q2.x, y, s22));
    s22 = fmaf(q1.w, v, -q2.y * y);
    v = y;
    // high shelf: b0=q2.z b1=q2.w b2=q3.x a1=q3.y a2=q3.z
    y = fmaf(q2.z, v, s31);
    s31 = fmaf(q2.w, v, fmaf(-q3.y, y, s32));
    s32 = fmaf(q3.x, v, -q3.z * y);
    return y;
}

// ---------------------------------------------------------------------------
// Kernel 2: time-chunked sequential IIR. One warp per chunk of L_CHUNK
// samples; lane = batch row (B == 32). Zero-state warmup of WARMUP samples
// (worst-case pole radius 0.9862 -> residual state error ~7e-7).
// Output staged through a 32x33 smem tile for coalesced [B][N] stores.
// ---------------------------------------------------------------------------
__global__ void __launch_bounds__(32) iir_kernel(float* __restrict__ out)
{
    int chunk = blockIdx.x;
    int lane  = threadIdx.x;
    int n_start = chunk * L_CHUNK;
    int n0 = n_start - WARMUP;
    if (n0 < 0) n0 = 0;

    float s11 = 0.f, s12 = 0.f, s21 = 0.f, s22 = 0.f, s31 = 0.f, s32 = 0.f;
    const float4* base = (const float4*)g_data;

    // warmup (no output)
    #pragma unroll 4
    for (int n = n0; n < n_start; ++n) {
        const float4* p = base + ((size_t)n * NB + lane) * 4;
        float4 q0 = p[0], q1 = p[1], q2 = p[2], q3 = p[3];
        cascade_step(q0, q1, q2, q3, s11, s12, s21, s22, s31, s32);
    }

    __shared__ float buf[32 * 33];

    for (int blk = 0; blk < L_CHUNK; blk += 32) {
        #pragma unroll 4
        for (int j = 0; j < 32; ++j) {
            int n = n_start + blk + j;
            const float4* p = base + ((size_t)n * NB + lane) * 4;
            float4 q0 = p[0], q1 = p[1], q2 = p[2], q3 = p[3];
            float ys = cascade_step(q0, q1, q2, q3, s11, s12, s21, s22, s31, s32);
            float2 m = g_mix[(size_t)n * NB + lane];
            buf[lane * 33 + j] = fmaf(m.y, ys, m.x);   // alpha_a*y_a + (1-alpha_a)*y_s
        }
        __syncwarp();
        int nw = n_start + blk + lane;
        #pragma unroll
        for (int b = 0; b < 32; ++b)
            out[(size_t)b * NS + nw] = buf[b * 33 + lane];
        __syncwarp();
    }
}

extern "C" void kernel_launch(void* const* d_in, const int* in_sizes, int n_in,
                              void* d_out, int out_size)
{
    const float* x       = (const float*)d_in[0];
    const float* alpha   = (const float*)d_in[1];
    const float* beta    = (const float*)d_in[2];
    const float* low_db  = (const float*)d_in[3];
    const float* mid_db  = (const float*)d_in[4];
    const float* mid_fc  = (const float*)d_in[5];
    const float* mid_Q   = (const float*)d_in[6];
    const float* high_db = (const float*)d_in[7];
    const float* alpha_a = (const float*)d_in[8];
    float* out = (float*)d_out;

    int total = NB * NS;
    int threads = 256;
    int blocks = (total + threads - 1) / threads;
    prep_kernel<<<blocks, threads>>>(x, alpha, beta, low_db, mid_db, mid_fc,
                                     mid_Q, high_db, alpha_a);
    iir_kernel<<<NCHUNK, 32>>>(out);
}

// round 2
// speedup vs baseline: 1.8944x; 1.8944x over previous
#include <cuda_runtime.h>
#include <math.h>

#define NB 32
#define NS 48000
#define L_CHUNK 320
#define WARMUP 768
#define NCHUNK (NS / L_CHUNK)   /* 150 */
#define PD 8                    /* prefetch depth (must divide 32) */

// Packed per-sample data: 15 biquad coefs + sustain input, layout [n][b][16]
__device__ float  g_data[(size_t)NS * NB * 16];
// Per-sample output mix: (alpha_a * y_attack, 1 - alpha_a), layout [n][b]
__device__ float2 g_mix[(size_t)NS * NB];

// ---------------- fast approx helpers (rel tol 1e-3 overall) ----------------
__device__ __forceinline__ float f_tanh(float x) {
    float r; asm("tanh.approx.f32 %0, %1;" : "=f"(r) : "f"(x)); return r;
}
__device__ __forceinline__ float f_rcp(float x) {
    float r; asm("rcp.approx.f32 %0, %1;" : "=f"(r) : "f"(x)); return r;
}
__device__ __forceinline__ float f_ex2(float x) {
    float r; asm("ex2.approx.f32 %0, %1;" : "=f"(r) : "f"(x)); return r;
}

// ---------------------------------------------------------------------------
// Kernel 1: transient sep, waveshaper, RBJ coef precompute.
// Block (16, 32): tx = sample-in-tile, ty = batch row. Grid = NS/16 tiles.
// Coefs staged through smem so global stores are fully coalesced.
// ---------------------------------------------------------------------------
__global__ void __launch_bounds__(512) prep_kernel(
        const float* __restrict__ x,
        const float* __restrict__ alpha,
        const float* __restrict__ beta,
        const float* __restrict__ low_db,
        const float* __restrict__ mid_db,
        const float* __restrict__ mid_fc,
        const float* __restrict__ mid_Q,
        const float* __restrict__ high_db,
        const float* __restrict__ alpha_a)
{
    __shared__ float  st[16 * 516];   // per-tx row: 512 floats + 4 pad
    __shared__ float2 ms[16 * 33];

    const int tx = threadIdx.x;          // 0..15  (n within tile)
    const int ty = threadIdx.y;          // 0..31  (batch row)
    const int nbase = blockIdx.x * 16;
    const int n = nbase + tx;
    const int b = ty;
    const int i = b * NS + n;

    // ---- transient separation (15-tap moving avg of |x|, zero padded) ----
    const float* xr = x + (size_t)b * NS;
    float xv = xr[n];
    float env = 0.0f;
    #pragma unroll
    for (int d = -7; d <= 7; ++d) {
        int j = n + d;
        if (j >= 0 && j < NS) env += fabsf(xr[j]);
    }
    env *= (1.0f / 15.0f);
    float xa = fabsf(xv);
    // sigmoid(8 d) = 0.5 + 0.5 * tanh(4 d)
    float gate = fmaf(0.5f, f_tanh(4.0f * (xa - env)), 0.5f);
    float av = gate * xv;
    float sv = (1.0f - gate) * xv;

    // ---- waveshaper ----
    float be_ = beta[i];
    float ya = f_tanh(fmaf(alpha[i], av, be_)) - f_tanh(be_);

    // ---- RBJ coefficients ----
    const float K = 0.0830482024f;       // log2(10)/40
    float c[16];

    {   // low shelf, fc=250
        const float cw  = 0.9994645875f;
        const float alc = 0.0231360485f;
        float sA = f_ex2(low_db[i] * (0.5f * K));
        float A  = sA * sA;
        float t  = 2.0f * sA * alc;
        float Ap1 = A + 1.0f, Am1 = A - 1.0f;
        float inv = f_rcp(Ap1 + Am1 * cw + t);
        c[0] = A * (Ap1 - Am1 * cw + t) * inv;
        c[1] = 2.0f * A * (Am1 - Ap1 * cw) * inv;
        c[2] = A * (Ap1 - Am1 * cw - t) * inv;
        c[3] = -2.0f * (Am1 + Ap1 * cw) * inv;
        c[4] = (Ap1 + Am1 * cw - t) * inv;
    }
    {   // mid peaking
        float A  = f_ex2(mid_db[i] * K);
        float w0 = mid_fc[i] * 1.30899693e-4f;   // 2*pi/48000
        float sw = __sinf(w0), cw = __cosf(w0);
        float alq = sw * 0.5f * f_rcp(mid_Q[i]);
        float alA = alq * A;
        float alrA = alq * f_rcp(A);
        float inv = f_rcp(1.0f + alrA);
        c[5] = (1.0f + alA) * inv;
        c[6] = -2.0f * cw * inv;
        c[7] = (1.0f - alA) * inv;
        c[8] = c[6];                      // a1 == b1
        c[9] = (1.0f - alrA) * inv;
    }
    {   // high shelf, fc=4000
        const float cw  = 0.8660254038f;
        const float alc = 0.3535533906f;
        float sA = f_ex2(high_db[i] * (0.5f * K));
        float A  = sA * sA;
        float t  = 2.0f * sA * alc;
        float Ap1 = A + 1.0f, Am1 = A - 1.0f;
        float inv = f_rcp(Ap1 - Am1 * cw + t);
        c[10] = A * (Ap1 + Am1 * cw + t) * inv;
        c[11] = -2.0f * A * (Am1 + Ap1 * cw) * inv;
        c[12] = A * (Ap1 + Am1 * cw - t) * inv;
        c[13] = 2.0f * (Am1 - Ap1 * cw) * inv;
        c[14] = (Ap1 - Am1 * cw - t) * inv;
    }
    c[15] = sv;

    // stage into smem (padded row stride 516 floats = 129 float4)
    {
        float4* s4 = (float4*)st;
        int base = tx * 129 + ty * 4;
        s4[base + 0] = make_float4(c[0],  c[1],  c[2],  c[3]);
        s4[base + 1] = make_float4(c[4],  c[5],  c[6],  c[7]);
        s4[base + 2] = make_float4(c[8],  c[9],  c[10], c[11]);
        s4[base + 3] = make_float4(c[12], c[13], c[14], c[15]);
    }
    float aav = alpha_a[i];
    ms[tx * 33 + ty] = make_float2(aav * ya, 1.0f - aav);

    __syncthreads();

    // coalesced copy-out: 2048 float4 per block
    {
        const float4* s4 = (const float4*)st;
        float4* g4 = (float4*)g_data + (size_t)blockIdx.x * 2048;
        int tid = ty * 16 + tx;
        #pragma unroll
        for (int k = 0; k < 4; ++k) {
            int j = tid + k * 512;
            int jtx = j >> 7, rem = j & 127;
            g4[j] = s4[jtx * 129 + rem];
        }
        int mtx = tid >> 5, mb = tid & 31;
        g_mix[(size_t)(nbase + mtx) * NB + mb] = ms[mtx * 33 + mb];
    }
}

// ---------------------------------------------------------------------------
// One biquad-cascade step (transposed DF2).
// ---------------------------------------------------------------------------
__device__ __forceinline__ float cascade_step(float4 q0, float4 q1, float4 q2, float4 q3,
                                              float& s11, float& s12,
                                              float& s21, float& s22,
                                              float& s31, float& s32)
{
    float v = q3.w;
    float y = fmaf(q0.x, v, s11);
    s11 = fmaf(q0.y, v, fmaf(-q0.w, y, s12));
    s12 = fmaf(q0.z, v, -q1.x * y);
    v = y;
    y = fmaf(q1.y, v, s21);
    s21 = fmaf(q1.z, v, fmaf(-q2.x, y, s22));
    s22 = fmaf(q1.w, v, -q2.y * y);
    v = y;
    y = fmaf(q2.z, v, s31);
    s31 = fmaf(q2.w, v, fmaf(-q3.y, y, s32));
    s32 = fmaf(q3.x, v, -q3.z * y);
    return y;
}

// ---------------------------------------------------------------------------
// Kernel 2: time-chunked sequential IIR with PD-deep register prefetch.
// One warp per chunk; lane = batch row. Zero-state warmup of WARMUP samples.
// ---------------------------------------------------------------------------
__global__ void __launch_bounds__(32) iir_kernel(float* __restrict__ out)
{
    const int chunk = blockIdx.x;
    const int lane  = threadIdx.x;
    const int n_start = chunk * L_CHUNK;
    int n0 = n_start - WARMUP;
    if (n0 < 0) n0 = 0;
    const int total = (n_start - n0) + L_CHUNK;      // multiple of 32
    const int n_end = n0 + total;

    const float4* __restrict__ bq = (const float4*)g_data;
    const float2* __restrict__ bm = g_mix;

    float s11 = 0.f, s12 = 0.f, s21 = 0.f, s22 = 0.f, s31 = 0.f, s32 = 0.f;

    // prefetch pipeline
    float4 q[PD][4];
    float2 m[PD];
    #pragma unroll
    for (int d = 0; d < PD; ++d) {
        int idx = ((n0 + d) * NB + lane) * 4;
        q[d][0] = bq[idx]; q[d][1] = bq[idx + 1];
        q[d][2] = bq[idx + 2]; q[d][3] = bq[idx + 3];
        m[d] = bm[(n0 + d) * NB + lane];
    }

    __shared__ float buf[32 * 33];
    const int warm_tiles = (n_start - n0) >> 5;
    const int ntiles = total >> 5;

    for (int t = 0; t < ntiles; ++t) {
        const int nb_ = n0 + (t << 5);
        const bool emit = (t >= warm_tiles);
        #pragma unroll
        for (int j = 0; j < 32; ++j) {
            const int slot = j & (PD - 1);
            float4 q0 = q[slot][0], q1 = q[slot][1];
            float4 q2 = q[slot][2], q3 = q[slot][3];
            float2 mm = m[slot];
            // refill slot with sample PD ahead
            int nf = nb_ + j + PD;
            if (nf < n_end) {
                int idx = (nf * NB + lane) * 4;
                q[slot][0] = bq[idx]; q[slot][1] = bq[idx + 1];
                q[slot][2] = bq[idx + 2]; q[slot][3] = bq[idx + 3];
                m[slot] = bm[nf * NB + lane];
            }
            float ys = cascade_step(q0, q1, q2, q3, s11, s12, s21, s22, s31, s32);
            if (emit) buf[lane * 33 + j] = fmaf(mm.y, ys, mm.x);
        }
        if (emit) {
            __syncwarp();
            const int nw = nb_ + lane;
            #pragma unroll
            for (int b = 0; b < 32; ++b)
                out[b * NS + nw] = buf[b * 33 + lane];
            __syncwarp();
        }
    }
}

extern "C" void kernel_launch(void* const* d_in, const int* in_sizes, int n_in,
                              void* d_out, int out_size)
{
    const float* x       = (const float*)d_in[0];
    const float* alpha   = (const float*)d_in[1];
    const float* beta    = (const float*)d_in[2];
    const float* low_db  = (const float*)d_in[3];
    const float* mid_db  = (const float*)d_in[4];
    const float* mid_fc  = (const float*)d_in[5];
    const float* mid_Q   = (const float*)d_in[6];
    const float* high_db = (const float*)d_in[7];
    const float* alpha_a = (const float*)d_in[8];
    float* out = (float*)d_out;

    dim3 pb(16, 32);
    prep_kernel<<<NS / 16, pb>>>(x, alpha, beta, low_db, mid_db, mid_fc,
                                 mid_Q, high_db, alpha_a);
    iir_kernel<<<NCHUNK, 32>>>(out);
}

// round 3
// speedup vs baseline: 3.1592x; 1.6677x over previous
#include <cuda_runtime.h>
#include <math.h>

#define NB 32
#define NS 48000
#define L_CHUNK 320
#define WARMUP 512
#define NCHUNK (NS / L_CHUNK)   /* 150 */
#define PD 8                    /* prefetch depth (must divide 32) */
#define PLANE (NS * NB)         /* float4 elements per plane */

// 4 planes of float4: plane k holds coef-quad k for (n, b), layout [n][b]
__device__ float4 g_planes[4 * (size_t)PLANE];
// Per-sample output mix: (alpha_a * y_attack, 1 - alpha_a), layout [n][b]
__device__ float2 g_mix[(size_t)PLANE];

// ---------------- fast approx helpers (rel tol 1e-3 overall) ----------------
__device__ __forceinline__ float f_tanh(float x) {
    float r; asm("tanh.approx.f32 %0, %1;" : "=f"(r) : "f"(x)); return r;
}
__device__ __forceinline__ float f_rcp(float x) {
    float r; asm("rcp.approx.f32 %0, %1;" : "=f"(r) : "f"(x)); return r;
}
__device__ __forceinline__ float f_ex2(float x) {
    float r; asm("ex2.approx.f32 %0, %1;" : "=f"(r) : "f"(x)); return r;
}

// ---------------------------------------------------------------------------
// Kernel 1: transient sep, waveshaper, RBJ coef precompute.
// Block (16, 32): tx = sample-in-tile, ty = batch row.
// Coefs staged via bank-conflict-free smem [k][tx][b] (stride 33), then
// written out as 4 planar streams, fully coalesced.
// ---------------------------------------------------------------------------
__global__ void __launch_bounds__(512) prep_kernel(
        const float* __restrict__ x,
        const float* __restrict__ alpha,
        const float* __restrict__ beta,
        const float* __restrict__ low_db,
        const float* __restrict__ mid_db,
        const float* __restrict__ mid_fc,
        const float* __restrict__ mid_Q,
        const float* __restrict__ high_db,
        const float* __restrict__ alpha_a)
{
    __shared__ float4 st4[4 * 16 * 33];   // [k][tx][b], stride 33 -> no conflicts
    __shared__ float2 ms[16 * 33];

    const int tx = threadIdx.x;          // 0..15  (n within tile)
    const int ty = threadIdx.y;          // 0..31  (batch row)
    const int nbase = blockIdx.x * 16;
    const int n = nbase + tx;
    const int b = ty;
    const int i = b * NS + n;

    // ---- transient separation (15-tap moving avg of |x|, zero padded) ----
    const float* xr = x + (size_t)b * NS;
    float xv = xr[n];
    float env = 0.0f;
    #pragma unroll
    for (int d = -7; d <= 7; ++d) {
        int j = n + d;
        if (j >= 0 && j < NS) env += fabsf(xr[j]);
    }
    env *= (1.0f / 15.0f);
    float xa = fabsf(xv);
    // sigmoid(8 d) = 0.5 + 0.5 * tanh(4 d)
    float gate = fmaf(0.5f, f_tanh(4.0f * (xa - env)), 0.5f);
    float av = gate * xv;
    float sv = (1.0f - gate) * xv;

    // ---- waveshaper ----
    float be_ = beta[i];
    float ya = f_tanh(fmaf(alpha[i], av, be_)) - f_tanh(be_);

    // ---- RBJ coefficients ----
    const float K = 0.0830482024f;       // log2(10)/40
    float c[16];

    {   // low shelf, fc=250
        const float cw  = 0.9994645875f;
        const float alc = 0.0231360485f;
        float sA = f_ex2(low_db[i] * (0.5f * K));
        float A  = sA * sA;
        float t  = 2.0f * sA * alc;
        float Ap1 = A + 1.0f, Am1 = A - 1.0f;
        float inv = f_rcp(Ap1 + Am1 * cw + t);
        c[0] = A * (Ap1 - Am1 * cw + t) * inv;
        c[1] = 2.0f * A * (Am1 - Ap1 * cw) * inv;
        c[2] = A * (Ap1 - Am1 * cw - t) * inv;
        c[3] = -2.0f * (Am1 + Ap1 * cw) * inv;
        c[4] = (Ap1 + Am1 * cw - t) * inv;
    }
    {   // mid peaking
        float A  = f_ex2(mid_db[i] * K);
        float w0 = mid_fc[i] * 1.30899693e-4f;   // 2*pi/48000
        float sw = __sinf(w0), cw = __cosf(w0);
        float alq = sw * 0.5f * f_rcp(mid_Q[i]);
        float alA = alq * A;
        float alrA = alq * f_rcp(A);
        float inv = f_rcp(1.0f + alrA);
        c[5] = (1.0f + alA) * inv;
        c[6] = -2.0f * cw * inv;
        c[7] = (1.0f - alA) * inv;
        c[8] = c[6];                      // a1 == b1 for peaking EQ
        c[9] = (1.0f - alrA) * inv;
    }
    {   // high shelf, fc=4000
        const float cw  = 0.8660254038f;
        const float alc = 0.3535533906f;
        float sA = f_ex2(high_db[i] * (0.5f * K));
        float A  = sA * sA;
        float t  = 2.0f * sA * alc;
        float Ap1 = A + 1.0f, Am1 = A - 1.0f;
        float inv = f_rcp(Ap1 - Am1 * cw + t);
        c[10] = A * (Ap1 + Am1 * cw + t) * inv;
        c[11] = -2.0f * A * (Am1 + Ap1 * cw) * inv;
        c[12] = A * (Ap1 + Am1 * cw - t) * inv;
        c[13] = 2.0f * (Am1 - Ap1 * cw) * inv;
        c[14] = (Ap1 - Am1 * cw - t) * inv;
    }
    c[15] = sv;

    // stage into smem: [k][tx][b] with row stride 33 float4
    #pragma unroll
    for (int k = 0; k < 4; ++k)
        st4[k * (16 * 33) + tx * 33 + b] =
            make_float4(c[4 * k], c[4 * k + 1], c[4 * k + 2], c[4 * k + 3]);
    float aav = alpha_a[i];
    ms[tx * 33 + ty] = make_float2(aav * ya, 1.0f - aav);

    __syncthreads();

    // coalesced planar copy-out: 4 planes x 512 float4 per block
    {
        const int tid = ty * 16 + tx;
        const int cb  = tid & 31;          // batch lane
        const int ctx = tid >> 5;          // sample within tile
        #pragma unroll
        for (int k = 0; k < 4; ++k) {
            g_planes[(size_t)k * PLANE + (nbase + ctx) * NB + cb] =
                st4[k * (16 * 33) + ctx * 33 + cb];
        }
        g_mix[(size_t)(nbase + ctx) * NB + cb] = ms[ctx * 33 + cb];
    }
}

// ---------------------------------------------------------------------------
// One biquad-cascade step (transposed DF2).
// ---------------------------------------------------------------------------
__device__ __forceinline__ float cascade_step(float4 q0, float4 q1, float4 q2, float4 q3,
                                              float& s11, float& s12,
                                              float& s21, float& s22,
                                              float& s31, float& s32)
{
    float v = q3.w;
    float y = fmaf(q0.x, v, s11);
    s11 = fmaf(q0.y, v, fmaf(-q0.w, y, s12));
    s12 = fmaf(q0.z, v, -q1.x * y);
    v = y;
    y = fmaf(q1.y, v, s21);
    s21 = fmaf(q1.z, v, fmaf(-q2.x, y, s22));
    s22 = fmaf(q1.w, v, -q2.y * y);
    v = y;
    y = fmaf(q2.z, v, s31);
    s31 = fmaf(q2.w, v, fmaf(-q3.y, y, s32));
    s32 = fmaf(q3.x, v, -q3.z * y);
    return y;
}

// ---------------------------------------------------------------------------
// Kernel 2: time-chunked sequential IIR with PD-deep register prefetch.
// One warp per chunk; lane = batch row. Planar coef loads: each LDG.128 is
// 512B contiguous (4 lines). Zero-state warmup of WARMUP samples.
// ---------------------------------------------------------------------------
__global__ void __launch_bounds__(32) iir_kernel(float* __restrict__ out)
{
    const int chunk = blockIdx.x;
    const int lane  = threadIdx.x;
    const int n_start = chunk * L_CHUNK;
    int n0 = n_start - WARMUP;
    if (n0 < 0) n0 = 0;
    const int total = (n_start - n0) + L_CHUNK;      // multiple of 32

    const float4* __restrict__ p0 = g_planes;
    const float4* __restrict__ p1 = g_planes + (size_t)PLANE;
    const float4* __restrict__ p2 = g_planes + 2 * (size_t)PLANE;
    const float4* __restrict__ p3 = g_planes + 3 * (size_t)PLANE;
    const float2* __restrict__ bm = g_mix;

    float s11 = 0.f, s12 = 0.f, s21 = 0.f, s22 = 0.f, s31 = 0.f, s32 = 0.f;

    // prefetch pipeline
    float4 q[PD][4];
    float2 m[PD];
    #pragma unroll
    for (int d = 0; d < PD; ++d) {
        int ofs = (n0 + d) * NB + lane;
        q[d][0] = p0[ofs]; q[d][1] = p1[ofs];
        q[d][2] = p2[ofs]; q[d][3] = p3[ofs];
        m[d] = bm[ofs];
    }

    __shared__ float buf[32 * 33];
    const int warm_tiles = (n_start - n0) >> 5;
    const int ntiles = total >> 5;

    for (int t = 0; t < ntiles; ++t) {
        const int nb_ = n0 + (t << 5);
        const bool emit = (t >= warm_tiles);
        #pragma unroll
        for (int j = 0; j < 32; ++j) {
            const int slot = j & (PD - 1);
            float4 q0 = q[slot][0], q1 = q[slot][1];
            float4 q2 = q[slot][2], q3 = q[slot][3];
            float2 mm = m[slot];
            // branch-free refill with sample PD ahead (clamped; extra loads
            // at chunk end are never consumed)
            int nf = nb_ + j + PD;
            if (nf > NS - 1) nf = NS - 1;
            int ofs = nf * NB + lane;
            q[slot][0] = p0[ofs]; q[slot][1] = p1[ofs];
            q[slot][2] = p2[ofs]; q[slot][3] = p3[ofs];
            m[slot] = bm[ofs];

            float ys = cascade_step(q0, q1, q2, q3, s11, s12, s21, s22, s31, s32);
            if (emit) buf[lane * 33 + j] = fmaf(mm.y, ys, mm.x);
        }
        if (emit) {
            __syncwarp();
            const int nw = nb_ + lane;
            #pragma unroll
            for (int b = 0; b < 32; ++b)
                out[b * NS + nw] = buf[b * 33 + lane];
            __syncwarp();
        }
    }
}

extern "C" void kernel_launch(void* const* d_in, const int* in_sizes, int n_in,
                              void* d_out, int out_size)
{
    const float* x       = (const float*)d_in[0];
    const float* alpha   = (const float*)d_in[1];
    const float* beta    = (const float*)d_in[2];
    const float* low_db  = (const float*)d_in[3];
    const float* mid_db  = (const float*)d_in[4];
    const float* mid_fc  = (const float*)d_in[5];
    const float* mid_Q   = (const float*)d_in[6];
    const float* high_db = (const float*)d_in[7];
    const float* alpha_a = (const float*)d_in[8];
    float* out = (float*)d_out;

    dim3 pb(16, 32);
    prep_kernel<<<NS / 16, pb>>>(x, alpha, beta, low_db, mid_db, mid_fc,
                                 mid_Q, high_db, alpha_a);
    iir_kernel<<<NCHUNK, 32>>>(out);
}

// round 5
// speedup vs baseline: 4.2386x; 1.3417x over previous
#include <cuda_runtime.h>
#include <math.h>

#define NB 32
#define NS 48000
#define L_CHUNK 128
#define NCH (NS / L_CHUNK)      /* 375 */
#define PD 8                    /* pass2 prefetch depth */
#define PD1 4                   /* pass1 prefetch depth */
#define PLANE (NS * NB)

// 4 planes of float4: plane k holds coef-quad k for (n, b), layout [n][b]
__device__ float4 g_planes[4 * (size_t)PLANE];
// Per-sample output mix: (alpha_a * y_attack, 1 - alpha_a), layout [n][b]
__device__ float2 g_mix[(size_t)PLANE];
// Per (chunk, lane) affine map: 30 floats (6 sparse columns + d), [c][b][30]
__device__ float g_maps[(size_t)NCH * NB * 30];
// Inclusive-scan chunk-end states: 6 planes of [c][b]
__device__ float g_state[6 * (size_t)NCH * NB];

// ---------------- fast approx helpers ----------------
__device__ __forceinline__ float f_tanh(float x) {
    float r; asm("tanh.approx.f32 %0, %1;" : "=f"(r) : "f"(x)); return r;
}
__device__ __forceinline__ float f_rcp(float x) {
    float r; asm("rcp.approx.f32 %0, %1;" : "=f"(r) : "f"(x)); return r;
}
__device__ __forceinline__ float f_ex2(float x) {
    float r; asm("ex2.approx.f32 %0, %1;" : "=f"(r) : "f"(x)); return r;
}

// ---------------------------------------------------------------------------
// Kernel 1: transient sep, waveshaper, RBJ coef precompute.
// Block (16, 32): tx = sample-in-tile, ty = batch row.
// ---------------------------------------------------------------------------
__global__ void __launch_bounds__(512) prep_kernel(
        const float* __restrict__ x,
        const float* __restrict__ alpha,
        const float* __restrict__ beta,
        const float* __restrict__ low_db,
        const float* __restrict__ mid_db,
        const float* __restrict__ mid_fc,
        const float* __restrict__ mid_Q,
        const float* __restrict__ high_db,
        const float* __restrict__ alpha_a)
{
    __shared__ float4 st4[4 * 16 * 33];
    __shared__ float2 ms[16 * 33];

    const int tx = threadIdx.x;
    const int ty = threadIdx.y;
    const int nbase = blockIdx.x * 16;
    const int n = nbase + tx;
    const int b = ty;
    const int i = b * NS + n;

    const float* xr = x + (size_t)b * NS;
    float xv = xr[n];
    float env = 0.0f;
    #pragma unroll
    for (int d = -7; d <= 7; ++d) {
        int j = n + d;
        if (j >= 0 && j < NS) env += fabsf(xr[j]);
    }
    env *= (1.0f / 15.0f);
    float xa = fabsf(xv);
    float gate = fmaf(0.5f, f_tanh(4.0f * (xa - env)), 0.5f);
    float av = gate * xv;
    float sv = (1.0f - gate) * xv;

    float be_ = beta[i];
    float ya = f_tanh(fmaf(alpha[i], av, be_)) - f_tanh(be_);

    const float K = 0.0830482024f;
    float c[16];
    {   // low shelf, fc=250
        const float cw  = 0.9994645875f;
        const float alc = 0.0231360485f;
        float sA = f_ex2(low_db[i] * (0.5f * K));
        float A  = sA * sA;
        float t  = 2.0f * sA * alc;
        float Ap1 = A + 1.0f, Am1 = A - 1.0f;
        float inv = f_rcp(Ap1 + Am1 * cw + t);
        c[0] = A * (Ap1 - Am1 * cw + t) * inv;
        c[1] = 2.0f * A * (Am1 - Ap1 * cw) * inv;
        c[2] = A * (Ap1 - Am1 * cw - t) * inv;
        c[3] = -2.0f * (Am1 + Ap1 * cw) * inv;
        c[4] = (Ap1 + Am1 * cw - t) * inv;
    }
    {   // mid peaking
        float A  = f_ex2(mid_db[i] * K);
        float w0 = mid_fc[i] * 1.30899693e-4f;
        float sw = __sinf(w0), cw = __cosf(w0);
        float alq = sw * 0.5f * f_rcp(mid_Q[i]);
        float alA = alq * A;
        float alrA = alq * f_rcp(A);
        float inv = f_rcp(1.0f + alrA);
        c[5] = (1.0f + alA) * inv;
        c[6] = -2.0f * cw * inv;
        c[7] = (1.0f - alA) * inv;
        c[8] = c[6];
        c[9] = (1.0f - alrA) * inv;
    }
    {   // high shelf, fc=4000
        const float cw  = 0.8660254038f;
        const float alc = 0.3535533906f;
        float sA = f_ex2(high_db[i] * (0.5f * K));
        float A  = sA * sA;
        float t  = 2.0f * sA * alc;
        float Ap1 = A + 1.0f, Am1 = A - 1.0f;
        float inv = f_rcp(Ap1 - Am1 * cw + t);
        c[10] = A * (Ap1 + Am1 * cw + t) * inv;
        c[11] = -2.0f * A * (Am1 + Ap1 * cw) * inv;
        c[12] = A * (Ap1 + Am1 * cw - t) * inv;
        c[13] = 2.0f * (Am1 - Ap1 * cw) * inv;
        c[14] = (Ap1 - Am1 * cw - t) * inv;
    }
    c[15] = sv;

    #pragma unroll
    for (int k = 0; k < 4; ++k)
        st4[k * (16 * 33) + tx * 33 + b] =
            make_float4(c[4 * k], c[4 * k + 1], c[4 * k + 2], c[4 * k + 3]);
    float aav = alpha_a[i];
    ms[tx * 33 + ty] = make_float2(aav * ya, 1.0f - aav);

    __syncthreads();
    {
        const int tid = ty * 16 + tx;
        const int cb  = tid & 31;
        const int ctx = tid >> 5;
        #pragma unroll
        for (int k = 0; k < 4; ++k) {
            g_planes[(size_t)k * PLANE + (nbase + ctx) * NB + cb] =
                st4[k * (16 * 33) + ctx * 33 + cb];
        }
        g_mix[(size_t)(nbase + ctx) * NB + cb] = ms[ctx * 33 + cb];
    }
}

// ---------------------------------------------------------------------------
// Step primitives. Coef mapping: low (b0,b1,b2,a1,a2) = (q0.x,q0.y,q0.z,q0.w,q1.x)
// mid = (q1.y,q1.z,q1.w,q2.x,q2.y), high = (q2.z,q2.w,q3.x,q3.y,q3.z), sv=q3.w.
// ---------------------------------------------------------------------------
__device__ __forceinline__ float stepF(const float4& q0, const float4& q1,
                                       const float4& q2, const float4& q3,
                                       float u[6], float v)
{
    float y1 = fmaf(q0.x, v, u[0]);
    float a  = fmaf(q0.y, v, fmaf(-q0.w, y1, u[1]));
    float bb = fmaf(q0.z, v, -q1.x * y1);
    float y2 = fmaf(q1.y, y1, u[2]);
    float cc = fmaf(q1.z, y1, fmaf(-q2.x, y2, u[3]));
    float dd = fmaf(q1.w, y1, -q2.y * y2);
    float y3 = fmaf(q2.z, y2, u[4]);
    float ee = fmaf(q2.w, y2, fmaf(-q3.y, y3, u[5]));
    float ff = fmaf(q3.x, y2, -q3.z * y3);
    u[0]=a; u[1]=bb; u[2]=cc; u[3]=dd; u[4]=ee; u[5]=ff;
    return y3;
}
__device__ __forceinline__ void stepM(const float4& q2, const float4& q3, float w[4])
{
    float y2 = w[0];
    float a  = fmaf(-q2.x, y2, w[1]);
    float bb = -q2.y * y2;
    float y3 = fmaf(q2.z, y2, w[2]);
    float cc = fmaf(q2.w, y2, fmaf(-q3.y, y3, w[3]));
    float dd = fmaf(q3.x, y2, -q3.z * y3);
    w[0]=a; w[1]=bb; w[2]=cc; w[3]=dd;
}
__device__ __forceinline__ void stepH(const float4& q3, float w[2])
{
    float y3 = w[0];
    float a  = fmaf(-q3.y, y3, w[1]);
    float bb = -q3.z * y3;
    w[0]=a; w[1]=bb;
}

// ---------------------------------------------------------------------------
// Pass 1: per-chunk affine map (6 sparse columns + d), one warp per chunk.
// Map record (30 floats): c1[6] c2[6] c3[4] c4[4] c5[2] c6[2] d[6]
// ---------------------------------------------------------------------------
__global__ void __launch_bounds__(32) map_kernel()
{
    const int c = blockIdx.x;
    const int lane = threadIdx.x;
    const int n0 = c * L_CHUNK;

    const float4* __restrict__ p0 = g_planes;
    const float4* __restrict__ p1 = g_planes + (size_t)PLANE;
    const float4* __restrict__ p2 = g_planes + 2 * (size_t)PLANE;
    const float4* __restrict__ p3 = g_planes + 3 * (size_t)PLANE;

    float u1[6] = {1,0,0,0,0,0};
    float u2[6] = {0,1,0,0,0,0};
    float u3[4] = {1,0,0,0};
    float u4[4] = {0,1,0,0};
    float u5[2] = {1,0};
    float u6[2] = {0,1};
    float dd[6] = {0,0,0,0,0,0};

    float4 q[PD1][4];
    #pragma unroll
    for (int d = 0; d < PD1; ++d) {
        int ofs = (n0 + d) * NB + lane;
        q[d][0] = p0[ofs]; q[d][1] = p1[ofs];
        q[d][2] = p2[ofs]; q[d][3] = p3[ofs];
    }

    for (int t = 0; t < L_CHUNK / 32; ++t) {
        const int nb_ = n0 + (t << 5);
        #pragma unroll
        for (int j = 0; j < 32; ++j) {
            const int slot = j & (PD1 - 1);
            float4 q0 = q[slot][0], q1 = q[slot][1];
            float4 q2 = q[slot][2], q3 = q[slot][3];
            int nf = nb_ + j + PD1;
            if (nf > NS - 1) nf = NS - 1;
            int ofs = nf * NB + lane;
            q[slot][0] = p0[ofs]; q[slot][1] = p1[ofs];
            q[slot][2] = p2[ofs]; q[slot][3] = p3[ofs];

            stepF(q0, q1, q2, q3, u1, 0.0f);
            stepF(q0, q1, q2, q3, u2, 0.0f);
            stepM(q2, q3, u3);
            stepM(q2, q3, u4);
            stepH(q3, u5);
            stepH(q3, u6);
            stepF(q0, q1, q2, q3, dd, q3.w);   // v = sv
        }
    }

    float* rec = g_maps + (size_t)(c * NB + lane) * 30;
    #pragma unroll
    for (int k = 0; k < 6; ++k) rec[k]      = u1[k];
    #pragma unroll
    for (int k = 0; k < 6; ++k) rec[6 + k]  = u2[k];
    #pragma unroll
    for (int k = 0; k < 4; ++k) rec[12 + k] = u3[k];
    #pragma unroll
    for (int k = 0; k < 4; ++k) rec[16 + k] = u4[k];
    rec[20] = u5[0]; rec[21] = u5[1];
    rec[22] = u6[0]; rec[23] = u6[1];
    #pragma unroll
    for (int k = 0; k < 6; ++k) rec[24 + k] = dd[k];
}

// ---------------------------------------------------------------------------
// Map compose helpers: r = B * w (respecting block-lower-triangular sparsity)
// ---------------------------------------------------------------------------
__device__ __forceinline__ void bmv_full(const float* B, const float* w, float* r)
{
    r[0] = w[0]*B[0] + w[1]*B[6];
    r[1] = w[0]*B[1] + w[1]*B[7];
    r[2] = w[0]*B[2] + w[1]*B[8]  + w[2]*B[12] + w[3]*B[16];
    r[3] = w[0]*B[3] + w[1]*B[9]  + w[2]*B[13] + w[3]*B[17];
    r[4] = w[0]*B[4] + w[1]*B[10] + w[2]*B[14] + w[3]*B[18] + w[4]*B[20] + w[5]*B[22];
    r[5] = w[0]*B[5] + w[1]*B[11] + w[2]*B[15] + w[3]*B[19] + w[4]*B[21] + w[5]*B[23];
}
__device__ __forceinline__ void bmv_mid(const float* B, const float* w, float* r)
{
    r[0] = w[0]*B[12] + w[1]*B[16];
    r[1] = w[0]*B[13] + w[1]*B[17];
    r[2] = w[0]*B[14] + w[1]*B[18] + w[2]*B[20] + w[3]*B[22];
    r[3] = w[0]*B[15] + w[1]*B[19] + w[2]*B[21] + w[3]*B[23];
}
__device__ __forceinline__ void bmv_high(const float* B, const float* w, float* r)
{
    r[0] = w[0]*B[20] + w[1]*B[22];
    r[1] = w[0]*B[21] + w[1]*B[23];
}
// C = B after A  (A applied first)
__device__ __forceinline__ void compose(const float* A, const float* B, float* C)
{
    bmv_full(B, A + 0,  C + 0);
    bmv_full(B, A + 6,  C + 6);
    bmv_mid (B, A + 12, C + 12);
    bmv_mid (B, A + 16, C + 16);
    bmv_high(B, A + 20, C + 20);
    bmv_high(B, A + 22, C + 22);
    float t6[6];
    bmv_full(B, A + 24, t6);
    #pragma unroll
    for (int k = 0; k < 6; ++k) C[24 + k] = t6[k] + B[24 + k];
}

// ---------------------------------------------------------------------------
// Scan: one block per batch lane. Hillis-Steele inclusive compose of NCH maps
// in smem; emits inclusive chunk-end states d -> g_state (6 planes of [c][b]).
// ---------------------------------------------------------------------------
__global__ void __launch_bounds__(384) scan_kernel()
{
    __shared__ float sm[NCH * 30];    // 45000 B
    const int t = threadIdx.x;
    const int b = blockIdx.x;

    if (t < NCH) {
        const float* src = g_maps + (size_t)(t * NB + b) * 30;
        #pragma unroll
        for (int k = 0; k < 30; ++k) sm[t * 30 + k] = src[k];
    }
    __syncthreads();

    for (int off = 1; off < NCH; off <<= 1) {
        float A[30], B[30];
        const bool act = (t < NCH) && (t >= off);
        if (act) {
            #pragma unroll
            for (int k = 0; k < 30; ++k) A[k] = sm[(t - off) * 30 + k];
            #pragma unroll
            for (int k = 0; k < 30; ++k) B[k] = sm[t * 30 + k];
        }
        __syncthreads();
        if (act) {
            float C[30];
            compose(A, B, C);
            #pragma unroll
            for (int k = 0; k < 30; ++k) sm[t * 30 + k] = C[k];
        }
        __syncthreads();
    }

    if (t < NCH) {
        #pragma unroll
        for (int k = 0; k < 6; ++k)
            g_state[(size_t)k * (NCH * NB) + t * NB + b] = sm[t * 30 + 24 + k];
    }
}

// ---------------------------------------------------------------------------
// Pass 2: final IIR per chunk with exact initial state (no warmup).
// ---------------------------------------------------------------------------
__global__ void __launch_bounds__(32) out_kernel(float* __restrict__ out)
{
    const int c = blockIdx.x;
    const int lane = threadIdx.x;
    const int n0 = c * L_CHUNK;

    const float4* __restrict__ p0 = g_planes;
    const float4* __restrict__ p1 = g_planes + (size_t)PLANE;
    const float4* __restrict__ p2 = g_planes + 2 * (size_t)PLANE;
    const float4* __restrict__ p3 = g_planes + 3 * (size_t)PLANE;
    const float2* __restrict__ bm = g_mix;

    float s[6] = {0,0,0,0,0,0};
    if (c > 0) {
        #pragma unroll
        for (int k = 0; k < 6; ++k)
            s[k] = g_state[(size_t)k * (NCH * NB) + (c - 1) * NB + lane];
    }

    float4 q[PD][4];
    float2 m[PD];
    #pragma unroll
    for (int d = 0; d < PD; ++d) {
        int ofs = (n0 + d) * NB + lane;
        q[d][0] = p0[ofs]; q[d][1] = p1[ofs];
        q[d][2] = p2[ofs]; q[d][3] = p3[ofs];
        m[d] = bm[ofs];
    }

    __shared__ float buf[32 * 33];

    for (int t = 0; t < L_CHUNK / 32; ++t) {
        const int nb_ = n0 + (t << 5);
        #pragma unroll
        for (int j = 0; j < 32; ++j) {
            const int slot = j & (PD - 1);
            float4 q0 = q[slot][0], q1 = q[slot][1];
            float4 q2 = q[slot][2], q3 = q[slot][3];
            float2 mm = m[slot];
            int nf = nb_ + j + PD;
            if (nf > NS - 1) nf = NS - 1;
            int ofs = nf * NB + lane;
            q[slot][0] = p0[ofs]; q[slot][1] = p1[ofs];
            q[slot][2] = p2[ofs]; q[slot][3] = p3[ofs];
            m[slot] = bm[ofs];

            float ys = stepF(q0, q1, q2, q3, s, q3.w);
            buf[lane * 33 + j] = fmaf(mm.y, ys, mm.x);
        }
        __syncwarp();
        const int nw = nb_ + lane;
        #pragma unroll
        for (int b = 0; b < 32; ++b)
            out[b * NS + nw] = buf[b * 33 + lane];
        __syncwarp();
    }
}

extern "C" void kernel_launch(void* const* d_in, const int* in_sizes, int n_in,
                              void* d_out, int out_size)
{
    const float* x       = (const float*)d_in[0];
    const float* alpha   = (const float*)d_in[1];
    const float* beta    = (const float*)d_in[2];
    const float* low_db  = (const float*)d_in[3];
    const float* mid_db  = (const float*)d_in[4];
    const float* mid_fc  = (const float*)d_in[5];
    const float* mid_Q   = (const float*)d_in[6];
    const float* high_db = (const float*)d_in[7];
    const float* alpha_a = (const float*)d_in[8];
    float* out = (float*)d_out;

    dim3 pb(16, 32);
    prep_kernel<<<NS / 16, pb>>>(x, alpha, beta, low_db, mid_db, mid_fc,
                                 mid_Q, high_db, alpha_a);
    map_kernel<<<NCH, 32>>>();
    scan_kernel<<<NB, 384>>>();
    out_kernel<<<NCH, 32>>>(out);
}

// round 6
// speedup vs baseline: 4.5597x; 1.0758x over previous
#include <cuda_runtime.h>
#include <math.h>

#define NB 32
#define NS 48000
#define L_CHUNK 128
#define NCH (NS / L_CHUNK)      /* 375 */
#define PD 8                    /* pass2 prefetch depth */
#define PD1 4                   /* pass1 prefetch depth */
#define PLANE (NS * NB)

// 2 planes of float4, layout [n][b]:
//   plane0 = (sA_low, cw_mid, alA, alrA)
//   plane1 = (sA_high, sv, alpha_a*y_attack, 1-alpha_a)
__device__ float4 g_p0[(size_t)PLANE];
__device__ float4 g_p1[(size_t)PLANE];
// Per (chunk, lane) affine map: 30 floats, [c][b][30]
__device__ float g_maps[(size_t)NCH * NB * 30];
// Inclusive-scan chunk-end states: 6 planes of [c][b]
__device__ float g_state[6 * (size_t)NCH * NB];

// shelf constants
#define CW_L  0.9994645875f     /* cos(2pi*250/48000) */
#define ALC_L 0.0231360485f     /* sin(w0_l)*sqrt(2)/2 */
#define CW_H  0.8660254038f     /* cos(pi/6) */
#define ALC_H 0.3535533906f     /* sin(pi/6)*sqrt(2)/2 */

// ---------------- fast approx helpers ----------------
__device__ __forceinline__ float f_tanh(float x) {
    float r; asm("tanh.approx.f32 %0, %1;" : "=f"(r) : "f"(x)); return r;
}
__device__ __forceinline__ float f_rcp(float x) {
    float r; asm("rcp.approx.f32 %0, %1;" : "=f"(r) : "f"(x)); return r;
}
__device__ __forceinline__ float f_ex2(float x) {
    float r; asm("ex2.approx.f32 %0, %1;" : "=f"(r) : "f"(x)); return r;
}

// ---------------------------------------------------------------------------
// Coefficient reconstruction from packed params (3 rcp + ~30 FMA).
// c[0..4]=low(b0,b1,b2,a1,a2) c[5..9]=mid c[10..14]=high
// ---------------------------------------------------------------------------
__device__ __forceinline__ void make_coefs(const float4& a, const float4& b, float c[15])
{
    {   // low shelf
        float sA = a.x;
        float A  = sA * sA;
        float t  = 2.0f * sA * ALC_L;
        float ap = A + 1.0f, am = A - 1.0f;
        float inv = f_rcp(ap + am * CW_L + t);
        c[0] = A * (ap - am * CW_L + t) * inv;
        c[1] = 2.0f * A * (am - ap * CW_L) * inv;
        c[2] = A * (ap - am * CW_L - t) * inv;
        c[3] = -2.0f * (am + ap * CW_L) * inv;
        c[4] = (ap + am * CW_L - t) * inv;
    }
    {   // mid peaking
        float cw = a.y, alA = a.z, alrA = a.w;
        float inv = f_rcp(1.0f + alrA);
        c[5] = (1.0f + alA) * inv;
        c[6] = -2.0f * cw * inv;
        c[7] = (1.0f - alA) * inv;
        c[8] = c[6];
        c[9] = (1.0f - alrA) * inv;
    }
    {   // high shelf
        float sA = b.x;
        float A  = sA * sA;
        float t  = 2.0f * sA * ALC_H;
        float ap = A + 1.0f, am = A - 1.0f;
        float inv = f_rcp(ap - am * CW_H + t);
        c[10] = A * (ap + am * CW_H + t) * inv;
        c[11] = -2.0f * A * (am + ap * CW_H) * inv;
        c[12] = A * (ap + am * CW_H - t) * inv;
        c[13] = 2.0f * (am - ap * CW_H) * inv;
        c[14] = (ap - am * CW_H - t) * inv;
    }
}

// ---------------------------------------------------------------------------
// Kernel 1: transient sep, waveshaper, derived-param precompute.
// Block (16, 32): tx = sample-in-tile, ty = batch row.
// ---------------------------------------------------------------------------
__global__ void __launch_bounds__(512) prep_kernel(
        const float* __restrict__ x,
        const float* __restrict__ alpha,
        const float* __restrict__ beta,
        const float* __restrict__ low_db,
        const float* __restrict__ mid_db,
        const float* __restrict__ mid_fc,
        const float* __restrict__ mid_Q,
        const float* __restrict__ high_db,
        const float* __restrict__ alpha_a)
{
    __shared__ float4 st4[2 * 16 * 33];

    const int tx = threadIdx.x;
    const int ty = threadIdx.y;
    const int nbase = blockIdx.x * 16;
    const int n = nbase + tx;
    const int b = ty;
    const int i = b * NS + n;

    const float* xr = x + (size_t)b * NS;
    float xv = xr[n];
    float env = 0.0f;
    #pragma unroll
    for (int d = -7; d <= 7; ++d) {
        int j = n + d;
        if (j >= 0 && j < NS) env += fabsf(xr[j]);
    }
    env *= (1.0f / 15.0f);
    float xa = fabsf(xv);
    float gate = fmaf(0.5f, f_tanh(4.0f * (xa - env)), 0.5f);
    float av = gate * xv;
    float sv = (1.0f - gate) * xv;

    float be_ = beta[i];
    float ya = f_tanh(fmaf(alpha[i], av, be_)) - f_tanh(be_);

    const float K = 0.0830482024f;       // log2(10)/40
    float sA_l = f_ex2(low_db[i] * (0.5f * K));
    float sA_h = f_ex2(high_db[i] * (0.5f * K));

    float A_m = f_ex2(mid_db[i] * K);
    float w0  = mid_fc[i] * 1.30899693e-4f;   // 2*pi/48000
    float sw = __sinf(w0), cw = __cosf(w0);
    float alq  = sw * 0.5f * f_rcp(mid_Q[i]);
    float alA  = alq * A_m;
    float alrA = alq * f_rcp(A_m);

    float aav = alpha_a[i];

    st4[0 * (16 * 33) + tx * 33 + b] = make_float4(sA_l, cw, alA, alrA);
    st4[1 * (16 * 33) + tx * 33 + b] = make_float4(sA_h, sv, aav * ya, 1.0f - aav);

    __syncthreads();
    {
        const int tid = ty * 16 + tx;
        const int cb  = tid & 31;
        const int ctx = tid >> 5;
        g_p0[(size_t)(nbase + ctx) * NB + cb] = st4[0 * (16 * 33) + ctx * 33 + cb];
        g_p1[(size_t)(nbase + ctx) * NB + cb] = st4[1 * (16 * 33) + ctx * 33 + cb];
    }
}

// ---------------------------------------------------------------------------
// Step primitives on coefficient array c[15].
// ---------------------------------------------------------------------------
__device__ __forceinline__ float stepF(const float c[15], float u[6], float v)
{
    float y1 = fmaf(c[0], v, u[0]);
    float a  = fmaf(c[1], v, fmaf(-c[3], y1, u[1]));
    float bb = fmaf(c[2], v, -c[4] * y1);
    float y2 = fmaf(c[5], y1, u[2]);
    float cc = fmaf(c[6], y1, fmaf(-c[8], y2, u[3]));
    float dd = fmaf(c[7], y1, -c[9] * y2);
    float y3 = fmaf(c[10], y2, u[4]);
    float ee = fmaf(c[11], y2, fmaf(-c[13], y3, u[5]));
    float ff = fmaf(c[12], y2, -c[14] * y3);
    u[0]=a; u[1]=bb; u[2]=cc; u[3]=dd; u[4]=ee; u[5]=ff;
    return y3;
}
__device__ __forceinline__ void stepM(const float c[15], float w[4])
{
    float y2 = w[0];
    float a  = fmaf(-c[8], y2, w[1]);
    float bb = -c[9] * y2;
    float y3 = fmaf(c[10], y2, w[2]);
    float cc = fmaf(c[11], y2, fmaf(-c[13], y3, w[3]));
    float dd = fmaf(c[12], y2, -c[14] * y3);
    w[0]=a; w[1]=bb; w[2]=cc; w[3]=dd;
}
__device__ __forceinline__ void stepH(const float c[15], float w[2])
{
    float y3 = w[0];
    float a  = fmaf(-c[13], y3, w[1]);
    float bb = -c[14] * y3;
    w[0]=a; w[1]=bb;
}

// ---------------------------------------------------------------------------
// Pass 1: per-chunk affine map (6 sparse columns + d), one warp per chunk.
// Map record (30 floats): c1[6] c2[6] c3[4] c4[4] c5[2] c6[2] d[6]
// ---------------------------------------------------------------------------
__global__ void __launch_bounds__(32) map_kernel()
{
    const int c = blockIdx.x;
    const int lane = threadIdx.x;
    const int n0 = c * L_CHUNK;

    const float4* __restrict__ p0 = g_p0;
    const float4* __restrict__ p1 = g_p1;

    float u1[6] = {1,0,0,0,0,0};
    float u2[6] = {0,1,0,0,0,0};
    float u3[4] = {1,0,0,0};
    float u4[4] = {0,1,0,0};
    float u5[2] = {1,0};
    float u6[2] = {0,1};
    float dd[6] = {0,0,0,0,0,0};

    float4 qa[PD1], qb[PD1];
    #pragma unroll
    for (int d = 0; d < PD1; ++d) {
        int ofs = (n0 + d) * NB + lane;
        qa[d] = p0[ofs]; qb[d] = p1[ofs];
    }

    for (int t = 0; t < L_CHUNK / 32; ++t) {
        const int nb_ = n0 + (t << 5);
        #pragma unroll
        for (int j = 0; j < 32; ++j) {
            const int slot = j & (PD1 - 1);
            float4 a = qa[slot], b = qb[slot];
            int nf = nb_ + j + PD1;
            if (nf > NS - 1) nf = NS - 1;
            int ofs = nf * NB + lane;
            qa[slot] = p0[ofs]; qb[slot] = p1[ofs];

            float cf[15];
            make_coefs(a, b, cf);

            stepF(cf, u1, 0.0f);
            stepF(cf, u2, 0.0f);
            stepM(cf, u3);
            stepM(cf, u4);
            stepH(cf, u5);
            stepH(cf, u6);
            stepF(cf, dd, b.y);   // v = sv
        }
    }

    float* rec = g_maps + (size_t)(c * NB + lane) * 30;
    #pragma unroll
    for (int k = 0; k < 6; ++k) rec[k]      = u1[k];
    #pragma unroll
    for (int k = 0; k < 6; ++k) rec[6 + k]  = u2[k];
    #pragma unroll
    for (int k = 0; k < 4; ++k) rec[12 + k] = u3[k];
    #pragma unroll
    for (int k = 0; k < 4; ++k) rec[16 + k] = u4[k];
    rec[20] = u5[0]; rec[21] = u5[1];
    rec[22] = u6[0]; rec[23] = u6[1];
    #pragma unroll
    for (int k = 0; k < 6; ++k) rec[24 + k] = dd[k];
}

// ---------------------------------------------------------------------------
// Map compose helpers (block-lower-triangular sparsity).
// ---------------------------------------------------------------------------
__device__ __forceinline__ void bmv_full(const float* B, const float* w, float* r)
{
    r[0] = w[0]*B[0] + w[1]*B[6];
    r[1] = w[0]*B[1] + w[1]*B[7];
    r[2] = w[0]*B[2] + w[1]*B[8]  + w[2]*B[12] + w[3]*B[16];
    r[3] = w[0]*B[3] + w[1]*B[9]  + w[2]*B[13] + w[3]*B[17];
    r[4] = w[0]*B[4] + w[1]*B[10] + w[2]*B[14] + w[3]*B[18] + w[4]*B[20] + w[5]*B[22];
    r[5] = w[0]*B[5] + w[1]*B[11] + w[2]*B[15] + w[3]*B[19] + w[4]*B[21] + w[5]*B[23];
}
__device__ __forceinline__ void bmv_mid(const float* B, const float* w, float* r)
{
    r[0] = w[0]*B[12] + w[1]*B[16];
    r[1] = w[0]*B[13] + w[1]*B[17];
    r[2] = w[0]*B[14] + w[1]*B[18] + w[2]*B[20] + w[3]*B[22];
    r[3] = w[0]*B[15] + w[1]*B[19] + w[2]*B[21] + w[3]*B[23];
}
__device__ __forceinline__ void bmv_high(const float* B, const float* w, float* r)
{
    r[0] = w[0]*B[20] + w[1]*B[22];
    r[1] = w[0]*B[21] + w[1]*B[23];
}
// C = B after A  (A applied first)
__device__ __forceinline__ void compose(const float* A, const float* B, float* C)
{
    bmv_full(B, A + 0,  C + 0);
    bmv_full(B, A + 6,  C + 6);
    bmv_mid (B, A + 12, C + 12);
    bmv_mid (B, A + 16, C + 16);
    bmv_high(B, A + 20, C + 20);
    bmv_high(B, A + 22, C + 22);
    float t6[6];
    bmv_full(B, A + 24, t6);
    #pragma unroll
    for (int k = 0; k < 6; ++k) C[24 + k] = t6[k] + B[24 + k];
}

// ---------------------------------------------------------------------------
// Scan: one block per batch lane. Hillis-Steele inclusive compose in smem.
// ---------------------------------------------------------------------------
__global__ void __launch_bounds__(384) scan_kernel()
{
    __shared__ float sm[NCH * 30];    // 45000 B
    const int t = threadIdx.x;
    const int b = blockIdx.x;

    if (t < NCH) {
        const float* src = g_maps + (size_t)(t * NB + b) * 30;
        #pragma unroll
        for (int k = 0; k < 30; ++k) sm[t * 30 + k] = src[k];
    }
    __syncthreads();

    for (int off = 1; off < NCH; off <<= 1) {
        float A[30], B[30];
        const bool act = (t < NCH) && (t >= off);
        if (act) {
            #pragma unroll
            for (int k = 0; k < 30; ++k) A[k] = sm[(t - off) * 30 + k];
            #pragma unroll
            for (int k = 0; k < 30; ++k) B[k] = sm[t * 30 + k];
        }
        __syncthreads();
        if (act) {
            float C[30];
            compose(A, B, C);
            #pragma unroll
            for (int k = 0; k < 30; ++k) sm[t * 30 + k] = C[k];
        }
        __syncthreads();
    }

    if (t < NCH) {
        #pragma unroll
        for (int k = 0; k < 6; ++k)
            g_state[(size_t)k * (NCH * NB) + t * NB + b] = sm[t * 30 + 24 + k];
    }
}

// ---------------------------------------------------------------------------
// Pass 2: final IIR per chunk with exact initial state (no warmup).
// ---------------------------------------------------------------------------
__global__ void __launch_bounds__(32) out_kernel(float* __restrict__ out)
{
    const int c = blockIdx.x;
    const int lane = threadIdx.x;
    const int n0 = c * L_CHUNK;

    const float4* __restrict__ p0 = g_p0;
    const float4* __restrict__ p1 = g_p1;

    float s[6] = {0,0,0,0,0,0};
    if (c > 0) {
        #pragma unroll
        for (int k = 0; k < 6; ++k)
            s[k] = g_state[(size_t)k * (NCH * NB) + (c - 1) * NB + lane];
    }

    float4 qa[PD], qb[PD];
    #pragma unroll
    for (int d = 0; d < PD; ++d) {
        int ofs = (n0 + d) * NB + lane;
        qa[d] = p0[ofs]; qb[d] = p1[ofs];
    }

    __shared__ float buf[32 * 33];

    for (int t = 0; t < L_CHUNK / 32; ++t) {
        const int nb_ = n0 + (t << 5);
        #pragma unroll
        for (int j = 0; j < 32; ++j) {
            const int slot = j & (PD - 1);
            float4 a = qa[slot], b = qb[slot];
            int nf = nb_ + j + PD;
            if (nf > NS - 1) nf = NS - 1;
            int ofs = nf * NB + lane;
            qa[slot] = p0[ofs]; qb[slot] = p1[ofs];

            float cf[15];
            make_coefs(a, b, cf);
            float ys = stepF(cf, s, b.y);
            buf[lane * 33 + j] = fmaf(b.w, ys, b.z);
        }
        __syncwarp();
        const int nw = nb_ + lane;
        #pragma unroll
        for (int b2 = 0; b2 < 32; ++b2)
            out[b2 * NS + nw] = buf[b2 * 33 + lane];
        __syncwarp();
    }
}

extern "C" void kernel_launch(void* const* d_in, const int* in_sizes, int n_in,
                              void* d_out, int out_size)
{
    const float* x       = (const float*)d_in[0];
    const float* alpha   = (const float*)d_in[1];
    const float* beta    = (const float*)d_in[2];
    const float* low_db  = (const float*)d_in[3];
    const float* mid_db  = (const float*)d_in[4];
    const float* mid_fc  = (const float*)d_in[5];
    const float* mid_Q   = (const float*)d_in[6];
    const float* high_db = (const float*)d_in[7];
    const float* alpha_a = (const float*)d_in[8];
    float* out = (float*)d_out;

    dim3 pb(16, 32);
    prep_kernel<<<NS / 16, pb>>>(x, alpha, beta, low_db, mid_db, mid_fc,
                                 mid_Q, high_db, alpha_a);
    map_kernel<<<NCH, 32>>>();
    scan_kernel<<<NB, 384>>>();
    out_kernel<<<NCH, 32>>>(out);
}

// round 7
// speedup vs baseline: 5.1712x; 1.1341x over previous
#include <cuda_runtime.h>
#include <math.h>

#define NB 32
#define NS 48000
#define L_CHUNK 64
#define NCH (NS / L_CHUNK)      /* 750 */
#define NPAIR (NCH / 2)         /* 375 */
#define PD 8                    /* out prefetch depth */
#define PD1 4                   /* map prefetch depth */
#define PLANE (NS * NB)

// 3 planes of float4, layout [n][b]:
//   plane0 = (sA_low, invL, sA_high, invH)
//   plane1 = (cw_mid, alA, alrA, invM)
//   plane2 = (sv, alpha_a*y_attack, 1-alpha_a, 0)
__device__ float4 g_p0[(size_t)PLANE];
__device__ float4 g_p1[(size_t)PLANE];
__device__ float4 g_p2[(size_t)PLANE];
// Per (chunk, lane) affine map: 30 floats, [c][b][30]
__device__ float g_maps[(size_t)NCH * NB * 30];
// Inclusive chunk-end states: 6 planes of [c][b]
__device__ float g_state[6 * (size_t)NCH * NB];

// shelf constants
#define CW_L  0.9994645875f     /* cos(2pi*250/48000) */
#define ALC_L 0.0231360485f     /* sin(w0_l)*sqrt(2)/2 */
#define CW_H  0.8660254038f     /* cos(pi/6) */
#define ALC_H 0.3535533906f     /* sin(pi/6)*sqrt(2)/2 */

// ---------------- fast approx helpers ----------------
__device__ __forceinline__ float f_tanh(float x) {
    float r; asm("tanh.approx.f32 %0, %1;" : "=f"(r) : "f"(x)); return r;
}
__device__ __forceinline__ float f_rcp(float x) {
    float r; asm("rcp.approx.f32 %0, %1;" : "=f"(r) : "f"(x)); return r;
}
__device__ __forceinline__ float f_ex2(float x) {
    float r; asm("ex2.approx.f32 %0, %1;" : "=f"(r) : "f"(x)); return r;
}

// ---------------------------------------------------------------------------
// Coefficient reconstruction: pure FMA/MUL, no MUFU (reciprocals precomputed).
// c[0..4]=low(b0,b1,b2,a1,a2) c[5..9]=mid c[10..14]=high
// ---------------------------------------------------------------------------
__device__ __forceinline__ void make_coefs(const float4& pa, const float4& pb, float c[15])
{
    {   // low shelf: pa.x = sA, pa.y = 1/a0
        float sA = pa.x, inv = pa.y;
        float A  = sA * sA;
        float t  = 2.0f * sA * ALC_L;
        float ap = A + 1.0f, am = A - 1.0f;
        c[0] = A * (ap - am * CW_L + t) * inv;
        c[1] = 2.0f * A * (am - ap * CW_L) * inv;
        c[2] = A * (ap - am * CW_L - t) * inv;
        c[3] = -2.0f * (am + ap * CW_L) * inv;
        c[4] = (ap + am * CW_L - t) * inv;
    }
    {   // mid peaking: pb = (cw, alA, alrA, 1/a0)
        float cw = pb.x, alA = pb.y, alrA = pb.z, inv = pb.w;
        c[5] = (1.0f + alA) * inv;
        c[6] = -2.0f * cw * inv;
        c[7] = (1.0f - alA) * inv;
        c[8] = c[6];
        c[9] = (1.0f - alrA) * inv;
    }
    {   // high shelf: pa.z = sA, pa.w = 1/a0
        float sA = pa.z, inv = pa.w;
        float A  = sA * sA;
        float t  = 2.0f * sA * ALC_H;
        float ap = A + 1.0f, am = A - 1.0f;
        c[10] = A * (ap + am * CW_H + t) * inv;
        c[11] = -2.0f * A * (am + ap * CW_H) * inv;
        c[12] = A * (ap + am * CW_H - t) * inv;
        c[13] = 2.0f * (am - ap * CW_H) * inv;
        c[14] = (ap - am * CW_H - t) * inv;
    }
}

// ---------------------------------------------------------------------------
// Kernel 1: transient sep, waveshaper, derived-param precompute.
// ---------------------------------------------------------------------------
__global__ void __launch_bounds__(512) prep_kernel(
        const float* __restrict__ x,
        const float* __restrict__ alpha,
        const float* __restrict__ beta,
        const float* __restrict__ low_db,
        const float* __restrict__ mid_db,
        const float* __restrict__ mid_fc,
        const float* __restrict__ mid_Q,
        const float* __restrict__ high_db,
        const float* __restrict__ alpha_a)
{
    __shared__ float4 st4[3 * 16 * 33];

    const int tx = threadIdx.x;
    const int ty = threadIdx.y;
    const int nbase = blockIdx.x * 16;
    const int n = nbase + tx;
    const int b = ty;
    const int i = b * NS + n;

    const float* xr = x + (size_t)b * NS;
    float xv = xr[n];
    float env = 0.0f;
    #pragma unroll
    for (int d = -7; d <= 7; ++d) {
        int j = n + d;
        if (j >= 0 && j < NS) env += fabsf(xr[j]);
    }
    env *= (1.0f / 15.0f);
    float xa = fabsf(xv);
    float gate = fmaf(0.5f, f_tanh(4.0f * (xa - env)), 0.5f);
    float av = gate * xv;
    float sv = (1.0f - gate) * xv;

    float be_ = beta[i];
    float ya = f_tanh(fmaf(alpha[i], av, be_)) - f_tanh(be_);

    const float K = 0.0830482024f;       // log2(10)/40
    float sA_l = f_ex2(low_db[i] * (0.5f * K));
    float sA_h = f_ex2(high_db[i] * (0.5f * K));

    // low/high shelf a0 reciprocals
    float invL, invH;
    {
        float A = sA_l * sA_l, t = 2.0f * sA_l * ALC_L;
        invL = f_rcp((A + 1.0f) + (A - 1.0f) * CW_L + t);
    }
    {
        float A = sA_h * sA_h, t = 2.0f * sA_h * ALC_H;
        invH = f_rcp((A + 1.0f) - (A - 1.0f) * CW_H + t);
    }

    float A_m = f_ex2(mid_db[i] * K);
    float w0  = mid_fc[i] * 1.30899693e-4f;   // 2*pi/48000
    float sw = __sinf(w0), cw = __cosf(w0);
    float alq  = sw * 0.5f * f_rcp(mid_Q[i]);
    float alA  = alq * A_m;
    float alrA = alq * f_rcp(A_m);
    float invM = f_rcp(1.0f + alrA);

    float aav = alpha_a[i];

    st4[0 * (16 * 33) + tx * 33 + b] = make_float4(sA_l, invL, sA_h, invH);
    st4[1 * (16 * 33) + tx * 33 + b] = make_float4(cw, alA, alrA, invM);
    st4[2 * (16 * 33) + tx * 33 + b] = make_float4(sv, aav * ya, 1.0f - aav, 0.0f);

    __syncthreads();
    {
        const int tid = ty * 16 + tx;
        const int cb  = tid & 31;
        const int ctx = tid >> 5;
        const size_t o = (size_t)(nbase + ctx) * NB + cb;
        g_p0[o] = st4[0 * (16 * 33) + ctx * 33 + cb];
        g_p1[o] = st4[1 * (16 * 33) + ctx * 33 + cb];
        g_p2[o] = st4[2 * (16 * 33) + ctx * 33 + cb];
    }
}

// ---------------------------------------------------------------------------
// Step primitives on coefficient array c[15].
// ---------------------------------------------------------------------------
__device__ __forceinline__ float stepF(const float c[15], float u[6], float v)
{
    float y1 = fmaf(c[0], v, u[0]);
    float a  = fmaf(c[1], v, fmaf(-c[3], y1, u[1]));
    float bb = fmaf(c[2], v, -c[4] * y1);
    float y2 = fmaf(c[5], y1, u[2]);
    float cc = fmaf(c[6], y1, fmaf(-c[8], y2, u[3]));
    float dd = fmaf(c[7], y1, -c[9] * y2);
    float y3 = fmaf(c[10], y2, u[4]);
    float ee = fmaf(c[11], y2, fmaf(-c[13], y3, u[5]));
    float ff = fmaf(c[12], y2, -c[14] * y3);
    u[0]=a; u[1]=bb; u[2]=cc; u[3]=dd; u[4]=ee; u[5]=ff;
    return y3;
}
__device__ __forceinline__ void stepM(const float c[15], float w[4])
{
    float y2 = w[0];
    float a  = fmaf(-c[8], y2, w[1]);
    float bb = -c[9] * y2;
    float y3 = fmaf(c[10], y2, w[2]);
    float cc = fmaf(c[11], y2, fmaf(-c[13], y3, w[3]));
    float dd = fmaf(c[12], y2, -c[14] * y3);
    w[0]=a; w[1]=bb; w[2]=cc; w[3]=dd;
}
__device__ __forceinline__ void stepH(const float c[15], float w[2])
{
    float y3 = w[0];
    float a  = fmaf(-c[13], y3, w[1]);
    float bb = -c[14] * y3;
    w[0]=a; w[1]=bb;
}

// ---------------------------------------------------------------------------
// Pass 1: per-chunk affine map, one warp per 64-sample chunk.
// Map record (30 floats): c1[6] c2[6] c3[4] c4[4] c5[2] c6[2] d[6]
// ---------------------------------------------------------------------------
__global__ void __launch_bounds__(32) map_kernel()
{
    const int c = blockIdx.x;
    const int lane = threadIdx.x;
    const int n0 = c * L_CHUNK;

    const float4* __restrict__ p0 = g_p0;
    const float4* __restrict__ p1 = g_p1;
    const float4* __restrict__ p2 = g_p2;

    float u1[6] = {1,0,0,0,0,0};
    float u2[6] = {0,1,0,0,0,0};
    float u3[4] = {1,0,0,0};
    float u4[4] = {0,1,0,0};
    float u5[2] = {1,0};
    float u6[2] = {0,1};
    float dd[6] = {0,0,0,0,0,0};

    float4 qa[PD1], qb[PD1], qc[PD1];
    #pragma unroll
    for (int d = 0; d < PD1; ++d) {
        int ofs = (n0 + d) * NB + lane;
        qa[d] = p0[ofs]; qb[d] = p1[ofs]; qc[d] = p2[ofs];
    }

    for (int t = 0; t < L_CHUNK / 32; ++t) {
        const int nb_ = n0 + (t << 5);
        #pragma unroll
        for (int j = 0; j < 32; ++j) {
            const int slot = j & (PD1 - 1);
            float4 a = qa[slot], b = qb[slot], cc2 = qc[slot];
            int nf = nb_ + j + PD1;
            if (nf > NS - 1) nf = NS - 1;
            int ofs = nf * NB + lane;
            qa[slot] = p0[ofs]; qb[slot] = p1[ofs]; qc[slot] = p2[ofs];

            float cf[15];
            make_coefs(a, b, cf);

            stepF(cf, u1, 0.0f);
            stepF(cf, u2, 0.0f);
            stepM(cf, u3);
            stepM(cf, u4);
            stepH(cf, u5);
            stepH(cf, u6);
            stepF(cf, dd, cc2.x);   // v = sv
        }
    }

    float* rec = g_maps + (size_t)(c * NB + lane) * 30;
    #pragma unroll
    for (int k = 0; k < 6; ++k) rec[k]      = u1[k];
    #pragma unroll
    for (int k = 0; k < 6; ++k) rec[6 + k]  = u2[k];
    #pragma unroll
    for (int k = 0; k < 4; ++k) rec[12 + k] = u3[k];
    #pragma unroll
    for (int k = 0; k < 4; ++k) rec[16 + k] = u4[k];
    rec[20] = u5[0]; rec[21] = u5[1];
    rec[22] = u6[0]; rec[23] = u6[1];
    #pragma unroll
    for (int k = 0; k < 6; ++k) rec[24 + k] = dd[k];
}

// ---------------------------------------------------------------------------
// Map compose helpers (block-lower-triangular sparsity).
// bmv_full(Msrc, w, r): r = M(src)·w using the 6 sparse columns of src.
// ---------------------------------------------------------------------------
__device__ __forceinline__ void bmv_full(const float* B, const float* w, float* r)
{
    r[0] = w[0]*B[0] + w[1]*B[6];
    r[1] = w[0]*B[1] + w[1]*B[7];
    r[2] = w[0]*B[2] + w[1]*B[8]  + w[2]*B[12] + w[3]*B[16];
    r[3] = w[0]*B[3] + w[1]*B[9]  + w[2]*B[13] + w[3]*B[17];
    r[4] = w[0]*B[4] + w[1]*B[10] + w[2]*B[14] + w[3]*B[18] + w[4]*B[20] + w[5]*B[22];
    r[5] = w[0]*B[5] + w[1]*B[11] + w[2]*B[15] + w[3]*B[19] + w[4]*B[21] + w[5]*B[23];
}
__device__ __forceinline__ void bmv_mid(const float* B, const float* w, float* r)
{
    r[0] = w[0]*B[12] + w[1]*B[16];
    r[1] = w[0]*B[13] + w[1]*B[17];
    r[2] = w[0]*B[14] + w[1]*B[18] + w[2]*B[20] + w[3]*B[22];
    r[3] = w[0]*B[15] + w[1]*B[19] + w[2]*B[21] + w[3]*B[23];
}
__device__ __forceinline__ void bmv_high(const float* B, const float* w, float* r)
{
    r[0] = w[0]*B[20] + w[1]*B[22];
    r[1] = w[0]*B[21] + w[1]*B[23];
}
// C = B after A  (A applied first)
__device__ __forceinline__ void compose(const float* A, const float* B, float* C)
{
    bmv_full(B, A + 0,  C + 0);
    bmv_full(B, A + 6,  C + 6);
    bmv_mid (B, A + 12, C + 12);
    bmv_mid (B, A + 16, C + 16);
    bmv_high(B, A + 20, C + 20);
    bmv_high(B, A + 22, C + 22);
    float t6[6];
    bmv_full(B, A + 24, t6);
    #pragma unroll
    for (int k = 0; k < 6; ++k) C[24 + k] = t6[k] + B[24 + k];
}

// ---------------------------------------------------------------------------
// Scan: one block per batch lane. Each thread pair-composes maps (2t, 2t+1)
// in registers, Hillis-Steele over 375 pairs in smem, then emits both
// chunk-end states (odd = pair-inclusive d; even = A_{2t} applied to prev).
// ---------------------------------------------------------------------------
__global__ void __launch_bounds__(384) scan_kernel()
{
    __shared__ float sm[NPAIR * 30];    // 45000 B
    const int t = threadIdx.x;
    const int b = blockIdx.x;
    const bool on = (t < NPAIR);

    float A[30];
    if (on) {
        const float* srcA = g_maps + (size_t)((2 * t)     * NB + b) * 30;
        const float* srcB = g_maps + (size_t)((2 * t + 1) * NB + b) * 30;
        float Bm[30], P[30];
        #pragma unroll
        for (int k = 0; k < 30; ++k) A[k]  = srcA[k];
        #pragma unroll
        for (int k = 0; k < 30; ++k) Bm[k] = srcB[k];
        compose(A, Bm, P);
        #pragma unroll
        for (int k = 0; k < 30; ++k) sm[t * 30 + k] = P[k];
    }
    __syncthreads();

    for (int off = 1; off < NPAIR; off <<= 1) {
        float Ap[30], Bp[30];
        const bool act = on && (t >= off);
        if (act) {
            #pragma unroll
            for (int k = 0; k < 30; ++k) Ap[k] = sm[(t - off) * 30 + k];
            #pragma unroll
            for (int k = 0; k < 30; ++k) Bp[k] = sm[t * 30 + k];
        }
        __syncthreads();
        if (act) {
            float C[30];
            compose(Ap, Bp, C);
            #pragma unroll
            for (int k = 0; k < 30; ++k) sm[t * 30 + k] = C[k];
        }
        __syncthreads();
    }

    if (on) {
        // odd chunk (2t+1): inclusive pair scan's d
        #pragma unroll
        for (int k = 0; k < 6; ++k)
            g_state[(size_t)k * (NCH * NB) + (2 * t + 1) * NB + b] = sm[t * 30 + 24 + k];
        // even chunk (2t): A_{2t} applied after S_{t-1}
        float se[6];
        if (t == 0) {
            #pragma unroll
            for (int k = 0; k < 6; ++k) se[k] = A[24 + k];
        } else {
            float w[6];
            #pragma unroll
            for (int k = 0; k < 6; ++k) w[k] = sm[(t - 1) * 30 + 24 + k];
            bmv_full(A, w, se);
            #pragma unroll
            for (int k = 0; k < 6; ++k) se[k] += A[24 + k];
        }
        #pragma unroll
        for (int k = 0; k < 6; ++k)
            g_state[(size_t)k * (NCH * NB) + (2 * t) * NB + b] = se[k];
    }
}

// ---------------------------------------------------------------------------
// Pass 2: final IIR per 64-sample chunk with exact initial state.
// ---------------------------------------------------------------------------
__global__ void __launch_bounds__(32) out_kernel(float* __restrict__ out)
{
    const int c = blockIdx.x;
    const int lane = threadIdx.x;
    const int n0 = c * L_CHUNK;

    const float4* __restrict__ p0 = g_p0;
    const float4* __restrict__ p1 = g_p1;
    const float4* __restrict__ p2 = g_p2;

    float s[6] = {0,0,0,0,0,0};
    if (c > 0) {
        #pragma unroll
        for (int k = 0; k < 6; ++k)
            s[k] = g_state[(size_t)k * (NCH * NB) + (c - 1) * NB + lane];
    }

    float4 qa[PD], qb[PD], qc[PD];
    #pragma unroll
    for (int d = 0; d < PD; ++d) {
        int ofs = (n0 + d) * NB + lane;
        qa[d] = p0[ofs]; qb[d] = p1[ofs]; qc[d] = p2[ofs];
    }

    __shared__ float buf[32 * 33];

    for (int t = 0; t < L_CHUNK / 32; ++t) {
        const int nb_ = n0 + (t << 5);
        #pragma unroll
        for (int j = 0; j < 32; ++j) {
            const int slot = j & (PD - 1);
            float4 a = qa[slot], b = qb[slot], m = qc[slot];
            int nf = nb_ + j + PD;
            if (nf > NS - 1) nf = NS - 1;
            int ofs = nf * NB + lane;
            qa[slot] = p0[ofs]; qb[slot] = p1[ofs]; qc[slot] = p2[ofs];

            float cf[15];
            make_coefs(a, b, cf);
            float ys = stepF(cf, s, m.x);
            buf[lane * 33 + j] = fmaf(m.z, ys, m.y);
        }
        __syncwarp();
        const int nw = nb_ + lane;
        #pragma unroll
        for (int b2 = 0; b2 < 32; ++b2)
            out[b2 * NS + nw] = buf[b2 * 33 + lane];
        __syncwarp();
    }
}

extern "C" void kernel_launch(void* const* d_in, const int* in_sizes, int n_in,
                              void* d_out, int out_size)
{
    const float* x       = (const float*)d_in[0];
    const float* alpha   = (const float*)d_in[1];
    const float* beta    = (const float*)d_in[2];
    const float* low_db  = (const float*)d_in[3];
    const float* mid_db  = (const float*)d_in[4];
    const float* mid_fc  = (const float*)d_in[5];
    const float* mid_Q   = (const float*)d_in[6];
    const float* high_db = (const float*)d_in[7];
    const float* alpha_a = (const float*)d_in[8];
    float* out = (float*)d_out;

    dim3 pb(16, 32);
    prep_kernel<<<NS / 16, pb>>>(x, alpha, beta, low_db, mid_db, mid_fc,
                                 mid_Q, high_db, alpha_a);
    map_kernel<<<NCH, 32>>>();
    scan_kernel<<<NB, 384>>>();
    out_kernel<<<NCH, 32>>>(out);
}